// round 16
// baseline (speedup 1.0000x reference)
#include <cuda_runtime.h>
#include <cuda_bf16.h>
#include <cstdint>
#include <math.h>
#include <stddef.h>

// ---------------- scratch (device globals; no allocations allowed) ----------
__device__ float g_h  [1024 * 256];
__device__ float g_hi [1024 * 256];
__device__ float g_hj [1024 * 256];
__device__ float g_agg[1024 * 256];
__device__ float g_n1 [1024 * 256];
__device__ float g_n2 [1024 * 256];
__device__ float g_enc[1024 * 256];
__device__ float g_k  [1024 * 256];
__device__ float g_v  [1024 * 256];
__device__ float g_q  [64 * 256];
__device__ float g_oA [64 * 256];
__device__ float g_m1 [64 * 256];
__device__ float g_m2 [64 * 256];
__device__ uint32_t g_w2bt[256 * 128];      // edge W2: [n][k/2] bf16x2
// split-bf16 chain weights: 18 matrices, [n][k/2] packed, hi + lo parts.
__device__ uint32_t g_wh[4736 * 128];
__device__ uint32_t g_wl[4736 * 128];

struct WPtrs { const float* p[18]; };

// ---------------- helpers ----------------------------------------------------
__device__ __forceinline__ uint32_t pack_bf16x2(float lo, float hi) {
    __nv_bfloat162 p = __floats2bfloat162_rn(lo, hi);
    return *(uint32_t*)&p;
}
__device__ __forceinline__ void mma_bf16(float* c, const uint32_t* a, const uint32_t* bf) {
    asm volatile(
        "mma.sync.aligned.m16n8k16.row.col.f32.bf16.bf16.f32 "
        "{%0,%1,%2,%3}, {%4,%5,%6,%7}, {%8,%9}, {%0,%1,%2,%3};"
        : "+f"(c[0]), "+f"(c[1]), "+f"(c[2]), "+f"(c[3])
        : "r"(a[0]), "r"(a[1]), "r"(a[2]), "r"(a[3]), "r"(bf[0]), "r"(bf[1]));
}
__device__ __forceinline__ void ldsm_x4(uint32_t* r, uint32_t saddr) {
    asm volatile("ldmatrix.sync.aligned.m8n8.x4.shared.b16 {%0,%1,%2,%3}, [%4];"
        : "=r"(r[0]), "=r"(r[1]), "=r"(r[2]), "=r"(r[3]) : "r"(saddr));
}
__device__ __forceinline__ void split_bf16(float x, __nv_bfloat16& h, __nv_bfloat16& l) {
    h = __float2bfloat16(x);
    l = __float2bfloat16(x - __bfloat162float(h));
}

// ---------------- prep: chain weights (split-bf16) + edge W2, one launch ----
__global__ void prep_all(WPtrs wp, const float* __restrict__ W2,
                         uint32_t* __restrict__ wh, uint32_t* __restrict__ wl,
                         uint32_t* __restrict__ w2bt) {
    const int c = threadIdx.x;
    if (blockIdx.x >= 4736) {
        int n = blockIdx.x - 4736;
        w2bt[n * 128 + c] = pack_bf16x2(W2[(2 * c) * 256 + n], W2[(2 * c + 1) * 256 + n]);
        return;
    }
    const int row = blockIdx.x;
    const int m = row < 4352 ? (row >> 8) : 17;
    const int n = row - (m < 17 ? (m << 8) : 4352);
    const int N = (m == 17) ? 384 : 256;
    const float* W = wp.p[m];
    float w0 = W[(size_t)(2 * c) * N + n];
    float w1 = W[(size_t)(2 * c + 1) * N + n];
    __nv_bfloat16 h0, l0, h1, l1;
    split_bf16(w0, h0, l0);
    split_bf16(w1, h1, l1);
    wh[(size_t)row * 128 + c] = pack_bf16x2(__bfloat162float(h0), __bfloat162float(h1));
    wl[(size_t)row * 128 + c] = pack_bf16x2(__bfloat162float(l0), __bfloat162float(l1));
}

// ---------------- split-bf16 tensor GEMM core (32m x 64n, 256 thr) -----------
static constexpr int B3P = 132;
static constexpr int B3_AH = 0;
static constexpr int B3_AL = 32 * B3P;
static constexpr int B3_WH = 2 * 32 * B3P;
static constexpr int B3_WL = B3_WH + 64 * B3P;
static constexpr int B3_U32 = B3_WL + 64 * B3P;
static constexpr int B3_SMEM = B3_U32 * 4;          // 101376 B (2 CTAs/SM)

__device__ __forceinline__ void b3_core(
    const float* __restrict__ A, const uint32_t* __restrict__ wh,
    const uint32_t* __restrict__ wl, const float* __restrict__ bias,
    const float* __restrict__ res, float* __restrict__ Cg,
    int M, int N, int act, int rowB, int colB, uint32_t* sm)
{
    const int tid = threadIdx.x, lane = tid & 31, w = tid >> 5;
    const int g = lane >> 2, tg = lane & 3;
    const int wm = w & 1, wn = w >> 1;

    {
        const int row = tid >> 3, f4 = tid & 7;
        #pragma unroll
        for (int p = 0; p < 8; ++p) {
            const int col = p * 8 + f4;
            const int gr = rowB + row;
            float4 av = (gr < M) ? *(const float4*)(A + (size_t)gr * 256 + col * 4)
                                 : make_float4(0.f, 0.f, 0.f, 0.f);
            __nv_bfloat16 h0,l0,h1,l1,h2,l2,h3,l3;
            split_bf16(av.x, h0, l0); split_bf16(av.y, h1, l1);
            split_bf16(av.z, h2, l2); split_bf16(av.w, h3, l3);
            uint2 oh, ol;
            oh.x = pack_bf16x2(__bfloat162float(h0), __bfloat162float(h1));
            oh.y = pack_bf16x2(__bfloat162float(h2), __bfloat162float(h3));
            ol.x = pack_bf16x2(__bfloat162float(l0), __bfloat162float(l1));
            ol.y = pack_bf16x2(__bfloat162float(l2), __bfloat162float(l3));
            *(uint2*)(sm + B3_AH + row * B3P + col * 2) = oh;
            *(uint2*)(sm + B3_AL + row * B3P + col * 2) = ol;
        }
    }
    {
        #pragma unroll
        for (int p = 0; p < 8; ++p) {
            const int idx = p * 256 + tid;
            const int n = idx >> 5, c4 = idx & 31;
            uint4 vh = *(const uint4*)(wh + (size_t)(colB + n) * 128 + c4 * 4);
            uint4 vl = *(const uint4*)(wl + (size_t)(colB + n) * 128 + c4 * 4);
            *(uint4*)(sm + B3_WH + n * B3P + c4 * 4) = vh;
            *(uint4*)(sm + B3_WL + n * B3P + c4 * 4) = vl;
        }
    }
    __syncthreads();

    const uint32_t smemS = (uint32_t)__cvta_generic_to_shared(sm);
    const uint32_t aTh = (uint32_t)((lane & 15) * (B3P * 4) + (lane >> 4) * 16);
    const uint32_t wTh = (uint32_t)((((lane >> 4) & 1) * 8 + (lane & 7)) * (B3P * 4)
                                    + ((lane >> 3) & 1) * 16);
    const uint32_t Ah = smemS + B3_AH * 4 + wm * 16 * (B3P * 4) + aTh;
    const uint32_t Al = smemS + B3_AL * 4 + wm * 16 * (B3P * 4) + aTh;
    const uint32_t Wh = smemS + B3_WH * 4 + wn * 16 * (B3P * 4) + wTh;
    const uint32_t Wl = smemS + B3_WL * 4 + wn * 16 * (B3P * 4) + wTh;

    float C[2][4] = {{0.f,0.f,0.f,0.f},{0.f,0.f,0.f,0.f}};
    #pragma unroll
    for (int ks = 0; ks < 16; ++ks) {
        uint32_t ahi[4], alo[4], th[4], tl[4];
        ldsm_x4(ahi, Ah + ks * 32);
        ldsm_x4(alo, Al + ks * 32);
        ldsm_x4(th, Wh + ks * 32);
        ldsm_x4(tl, Wl + ks * 32);
        uint32_t whi[2][2] = {{th[0], th[1]}, {th[2], th[3]}};
        uint32_t wlo[2][2] = {{tl[0], tl[1]}, {tl[2], tl[3]}};
        #pragma unroll
        for (int nt = 0; nt < 2; ++nt) {
            mma_bf16(C[nt], ahi, whi[nt]);
            mma_bf16(C[nt], ahi, wlo[nt]);
            mma_bf16(C[nt], alo, whi[nt]);
        }
    }

    #pragma unroll
    for (int nt = 0; nt < 2; ++nt) {
        #pragma unroll
        for (int rr = 0; rr < 2; ++rr) {
            const int m = rowB + wm * 16 + g + rr * 8;
            if (m < M) {
                #pragma unroll
                for (int cc = 0; cc < 2; ++cc) {
                    const int col = colB + wn * 16 + nt * 8 + 2 * tg + cc;
                    float v = C[nt][rr * 2 + cc] + (bias ? bias[col] : 0.f);
                    if (act) v = fmaxf(v, 0.f);
                    if (res) v += res[(size_t)m * N + col];
                    Cg[(size_t)m * N + col] = v;
                }
            }
        }
    }
}

__global__ void __launch_bounds__(256)
gemm_b3(const float* A, const uint32_t* wh, const uint32_t* wl,
        const float* bias, const float* res, float* Cg, int M, int N, int act)
{
    extern __shared__ uint32_t sm[];
    b3_core(A, wh, wl, bias, res, Cg, M, N, act,
            blockIdx.y * 32, blockIdx.x * 64, sm);
}

// fused multi-matrix (N=256): per-sel A/M; early-exit rows beyond M(sel).
__global__ void __launch_bounds__(256)
gemm_b3_qkv(const float* A0, const float* A1, const float* A2,
            const uint32_t* wh0, const uint32_t* wh1, const uint32_t* wh2,
            const uint32_t* wl0, const uint32_t* wl1, const uint32_t* wl2,
            const float* b0, const float* b1, const float* b2,
            float* C0, float* C1, float* C2, int M0, int M1, int M2)
{
    extern __shared__ uint32_t sm[];
    const int sel = blockIdx.x >> 2;
    const float* A     = sel == 0 ? A0 : (sel == 1 ? A1 : A2);
    const int M        = sel == 0 ? M0 : (sel == 1 ? M1 : M2);
    if ((int)blockIdx.y * 32 >= M) return;
    const uint32_t* wh = sel == 0 ? wh0 : (sel == 1 ? wh1 : wh2);
    const uint32_t* wl = sel == 0 ? wl0 : (sel == 1 ? wl1 : wl2);
    const float* bias  = sel == 0 ? b0 : (sel == 1 ? b1 : b2);
    float* Cg          = sel == 0 ? C0 : (sel == 1 ? C1 : C2);
    b3_core(A, wh, wl, bias, nullptr, Cg, M, 256, 0,
            blockIdx.y * 32, (blockIdx.x & 3) * 64, sm);
}

// ---------------- edge v9: persistent CTAs, W filled once per SM ------------
static constexpr int APW = 68;
static constexpr int WPW = 132;
static constexpr int EV_A  = 128 * APW;
static constexpr int EV_W  = 256 * WPW;
static constexpr int EV_U32 = 2 * EV_A + EV_W;            // 51200
static constexpr int EDGE9_SMEM = (EV_U32 + 1540) * 4;    // 210960 B

__global__ void __launch_bounds__(512, 1)
edge_pers(const float* __restrict__ hi, const float* __restrict__ hjp,
          const uint32_t* __restrict__ w2bt, const float* __restrict__ b2,
          const float* __restrict__ adj, float* __restrict__ agg)
{
    extern __shared__ uint32_t smu[];
    uint32_t* Abufs = smu;
    uint32_t* Wbuf  = smu + 2 * EV_A;
    float* ci    = (float*)(smu + EV_U32);
    float* b2s   = ci + 256;
    float* wlist = b2s + 256;
    float* part  = wlist + 256;                 // 512
    int*   idxs  = (int*)(part + 512);          // 256
    int*   cntp  = idxs + 256;

    const int tid = threadIdx.x, lane = tid & 31, w = tid >> 5;

    const int g  = lane >> 2;
    const int tg = lane & 3;
    const int jm = w & 1;          // j half (64) within a 128-row pass
    const int hn = w >> 1;         // h tile 0..7 (32 wide)
    const int kq = lane;           // float4 column within 128-k chunk
    const int jr = w;              // row base per fill pass (0..15)

    const uint32_t smemS = (uint32_t)__cvta_generic_to_shared(smu);
    const uint32_t aTh = (uint32_t)((lane & 15) * (APW * 4) + (lane >> 4) * 16);
    const uint32_t wTh = (uint32_t)((((lane >> 4) & 1) * 8 + (lane & 7)) * (WPW * 4)
                                    + ((lane >> 3) & 1) * 16);
    const uint32_t Wbase = smemS + 2 * EV_A * 4 + hn * 32 * (WPW * 4) + wTh;

    // ---- one-time: resident W + b2 ----
    #pragma unroll
    for (int p = 0; p < 16; ++p) {
        const int r = p * 16 + jr;
        uint4 wv = *(const uint4*)(w2bt + (size_t)r * 128 + kq * 4);
        *(uint4*)(Wbuf + r * WPW + kq * 4) = wv;
    }
    if (tid < 256) b2s[tid] = b2[tid];

    float C[4][4][4];
    #pragma unroll
    for (int mt = 0; mt < 4; ++mt)
        #pragma unroll
        for (int nt = 0; nt < 4; ++nt)
            #pragma unroll
            for (int r = 0; r < 4; ++r) C[mt][nt][r] = 0.f;

    for (int tile = blockIdx.x; tile < 1024; tile += gridDim.x) {
        const int i = tile & 255, b = tile >> 8;
        const size_t row = (size_t)(b * 256 + i) * 256;
        const float* hjb = hjp + (size_t)b * 65536;

        __syncthreads();             // previous tile fully done with smem tail
        if (tid == 0) *cntp = 0;
        __syncthreads();
        if (tid < 256) {
            ci[tid] = hi[row + tid];
            float a = adj[row + tid];
            if (a != 0.f) {
                int p = atomicAdd(cntp, 1);
                idxs[p]  = tid;
                wlist[p] = a;
            }
        }
        __syncthreads();
        const int nj = *cntp;
        const int npass = (nj + 127) >> 7;
        for (int r = nj + tid; r < npass * 128; r += 512) { wlist[r] = 0.f; idxs[r] = 0; }

        const float4 cv0 = *(const float4*)(ci + kq * 4);
        const float4 cv1 = *(const float4*)(ci + 128 + kq * 4);

        auto fillA_pass = [&](int s, int p) {
            const int jt = s >> 1, kc = s & 1;
            const int r = p * 16 + jr;
            const int slot = jt * 128 + r;
            uint2 o = {0u, 0u};
            if (slot < nj) {
                const int j = idxs[slot];
                const float4 cv = kc ? cv1 : cv0;
                float4 hv = *(const float4*)(hjb + (size_t)j * 256 + kc * 128 + kq * 4);
                o.x = pack_bf16x2(fmaxf(cv.x + hv.x, 0.f), fmaxf(cv.y + hv.y, 0.f));
                o.y = pack_bf16x2(fmaxf(cv.z + hv.z, 0.f), fmaxf(cv.w + hv.w, 0.f));
            }
            *(uint2*)(Abufs + (s & 1) * EV_A + r * APW + kq * 2) = o;
        };

        float ps[4][2];
        #pragma unroll
        for (int nt = 0; nt < 4; ++nt) { ps[nt][0] = 0.f; ps[nt][1] = 0.f; }

        const int tsteps = 2 * npass;
        if (npass > 0) {
            #pragma unroll
            for (int p = 0; p < 8; ++p) fillA_pass(0, p);
        }
        __syncthreads();

        for (int s = 0; s < tsteps; ++s) {
            const int kc = s & 1, jt = s >> 1;
            const uint32_t Abase = smemS + (uint32_t)((s & 1) * EV_A * 4)
                                 + jm * 64 * (APW * 4) + aTh;
            const uint32_t Wk = Wbase + (uint32_t)(kc * 256);
            #pragma unroll
            for (int ks = 0; ks < 8; ++ks) {
                uint32_t afr[4][4], bfr[4][2];
                #pragma unroll
                for (int mt = 0; mt < 4; ++mt)
                    ldsm_x4(afr[mt], Abase + mt * 16 * (APW * 4) + ks * 32);
                #pragma unroll
                for (int p = 0; p < 2; ++p) {
                    uint32_t tmp[4];
                    ldsm_x4(tmp, Wk + p * 16 * (WPW * 4) + ks * 32);
                    bfr[2 * p][0] = tmp[0]; bfr[2 * p][1] = tmp[1];
                    bfr[2 * p + 1][0] = tmp[2]; bfr[2 * p + 1][1] = tmp[3];
                }
                #pragma unroll
                for (int mt = 0; mt < 4; ++mt)
                    #pragma unroll
                    for (int nt = 0; nt < 4; ++nt)
                        mma_bf16(C[mt][nt], afr[mt], bfr[nt]);
                if (s + 1 < tsteps) fillA_pass(s + 1, ks);
            }
            if (kc == 1) {
                #pragma unroll
                for (int mt = 0; mt < 4; ++mt) {
                    const float aj0 = wlist[jt * 128 + jm * 64 + mt * 16 + g];
                    const float aj8 = wlist[jt * 128 + jm * 64 + mt * 16 + g + 8];
                    #pragma unroll
                    for (int nt = 0; nt < 4; ++nt) {
                        #pragma unroll
                        for (int c = 0; c < 2; ++c) {
                            const float bv = b2s[hn * 32 + nt * 8 + 2 * tg + c];
                            ps[nt][c] += aj0 * fmaxf(C[mt][nt][c]     + bv, 0.f)
                                       + aj8 * fmaxf(C[mt][nt][2 + c] + bv, 0.f);
                            C[mt][nt][c] = 0.f;
                            C[mt][nt][2 + c] = 0.f;
                        }
                    }
                }
            }
            __syncthreads();
        }

        // final reduce over g, combine jm halves, store
        #pragma unroll
        for (int off = 16; off >= 4; off >>= 1)
            #pragma unroll
            for (int nt = 0; nt < 4; ++nt)
                #pragma unroll
                for (int c = 0; c < 2; ++c)
                    ps[nt][c] += __shfl_down_sync(0xffffffffu, ps[nt][c], off);
        if (lane < 4) {
            #pragma unroll
            for (int nt = 0; nt < 4; ++nt)
                #pragma unroll
                for (int c = 0; c < 2; ++c)
                    part[w * 32 + nt * 8 + 2 * lane + c] = ps[nt][c];
        }
        __syncthreads();
        if (tid < 256) {
            const int hq = tid >> 5, hl = tid & 31;
            agg[row + tid] = part[(2 * hq) * 32 + hl] + part[(2 * hq + 1) * 32 + hl];
        }
    }
}

// ---------------- fp32 GEMM (used only for h: K=48) -------------------------
__global__ void gemm_kernel(const float* __restrict__ A, const float* __restrict__ W,
                            const float* __restrict__ bias, const float* __restrict__ res,
                            float* __restrict__ C, int M, int K, int N, int act)
{
    __shared__ float As[32 * 18];
    __shared__ float Ws[32 * 33];
    const int tid  = threadIdx.x;
    const int lane = tid & 31;
    const int ty   = tid >> 5;
    const int colB = blockIdx.x * 32;
    const int rowB = blockIdx.y * 16;

    float acc[2] = {0.f, 0.f};
    for (int k0 = 0; k0 < K; k0 += 32) {
        #pragma unroll
        for (int u = 0; u < 2; ++u) {
            int idx = tid + u * 256, r = idx >> 5, c = idx & 31;
            int gr = rowB + r, gk = k0 + c;
            As[c * 18 + r] = (gr < M && gk < K) ? A[(size_t)gr * K + gk] : 0.f;
        }
        #pragma unroll
        for (int u = 0; u < 4; ++u) {
            int idx = tid + u * 256, r = idx >> 5, c = idx & 31;
            int gk = k0 + r, gn = colB + c;
            Ws[r * 33 + c] = (gk < K && gn < N) ? W[(size_t)gk * N + gn] : 0.f;
        }
        __syncthreads();
        #pragma unroll
        for (int kk = 0; kk < 32; ++kk) {
            float2 av = *(const float2*)(As + kk * 18 + ty * 2);
            float wv = Ws[kk * 33 + lane];
            acc[0] = fmaf(av.x, wv, acc[0]);
            acc[1] = fmaf(av.y, wv, acc[1]);
        }
        __syncthreads();
    }
    int col = colB + lane;
    if (col < N) {
        float bv = bias ? bias[col] : 0.f;
        #pragma unroll
        for (int r = 0; r < 2; ++r) {
            int rowi = rowB + ty * 2 + r;
            if (rowi < M) {
                float v = acc[r] + bv;
                if (act) v = fmaxf(v, 0.f);
                if (res) v += res[(size_t)rowi * N + col];
                C[(size_t)rowi * N + col] = v;
            }
        }
    }
}

// ---------------- multi-head attention core ---------------------------------
__global__ void attn_kernel(const float* __restrict__ q, int q_bs,
                            const float* __restrict__ k, const float* __restrict__ v,
                            int Lk, float* __restrict__ o)
{
    __shared__ float qs[16 * 32];
    __shared__ float sc[16 * 256];
    const int tid  = threadIdx.x;
    const int head = blockIdx.x;
    const int b    = blockIdx.y;

    const float* qb = q + (size_t)b * q_bs;
    for (int u = tid; u < 512; u += 256) {
        int l = u >> 5, d = u & 31;
        qs[u] = qb[(size_t)l * 256 + head * 32 + d];
    }
    __syncthreads();

    {
        int l = tid & 15, jg = tid >> 4;
        const float* kb = k + ((size_t)b * Lk) * 256 + head * 32;
        for (int j = jg; j < Lk; j += 16) {
            const float* kr = kb + (size_t)j * 256;
            float s = 0.f;
            #pragma unroll
            for (int d = 0; d < 32; ++d) s = fmaf(qs[l * 32 + d], kr[d], s);
            sc[l * 256 + j] = s * 0.0625f;
        }
    }
    __syncthreads();

    if (tid < 16) {
        float m = -1e30f;
        for (int j = 0; j < Lk; ++j) m = fmaxf(m, sc[tid * 256 + j]);
        float sum = 0.f;
        for (int j = 0; j < Lk; ++j) {
            float e = __expf(sc[tid * 256 + j] - m);
            sc[tid * 256 + j] = e;
            sum += e;
        }
        float inv = 1.f / sum;
        for (int j = 0; j < Lk; ++j) sc[tid * 256 + j] *= inv;
    }
    __syncthreads();

    {
        const float* vb = v + ((size_t)b * Lk) * 256 + head * 32;
        for (int u = tid; u < 512; u += 256) {
            int l = u >> 5, d = u & 31;
            float accv = qs[l * 32 + d];
            for (int j = 0; j < Lk; ++j)
                accv = fmaf(sc[l * 256 + j], vb[(size_t)j * 256 + d], accv);
            o[((size_t)(b * 16 + l)) * 256 + head * 32 + d] = accv;
        }
    }
}

// ---------------- host orchestration ---------------------------------------
extern "C" void kernel_launch(void* const* d_in, const int* in_sizes, int n_in,
                              void* d_out, int out_size)
{
    (void)in_sizes; (void)n_in; (void)out_size;
    const float* x    = (const float*)d_in[0];
    const float* adj  = (const float*)d_in[1];
    const float* ginW = (const float*)d_in[2];
    const float* ginb = (const float*)d_in[3];
    const float* geW1 = (const float*)d_in[4];
    const float* geb1 = (const float*)d_in[5];
    const float* geW2 = (const float*)d_in[6];
    const float* geb2 = (const float*)d_in[7];
    const float* gnW1 = (const float*)d_in[8];
    const float* gnb1 = (const float*)d_in[9];
    const float* gnW2 = (const float*)d_in[10];
    const float* gnb2 = (const float*)d_in[11];
    const float* goW  = (const float*)d_in[12];
    const float* gob  = (const float*)d_in[13];
    const float* S    = (const float*)d_in[14];
    const float* mWq  = (const float*)d_in[15];
    const float* mbq  = (const float*)d_in[16];
    const float* mWk  = (const float*)d_in[17];
    const float* mbk  = (const float*)d_in[18];
    const float* mWv  = (const float*)d_in[19];
    const float* mbv  = (const float*)d_in[20];
    const float* mWo  = (const float*)d_in[21];
    const float* mbo  = (const float*)d_in[22];
    const float* finW = (const float*)d_in[23];
    const float* finb = (const float*)d_in[24];
    float* out = (float*)d_out;

    float *h, *hi, *hj, *agg, *n1, *n2, *enc, *kb, *vb, *q, *oA, *m1, *m2;
    uint32_t *w2bt, *wh, *wl;
    cudaGetSymbolAddress((void**)&h,   g_h);
    cudaGetSymbolAddress((void**)&hi,  g_hi);
    cudaGetSymbolAddress((void**)&hj,  g_hj);
    cudaGetSymbolAddress((void**)&agg, g_agg);
    cudaGetSymbolAddress((void**)&n1,  g_n1);
    cudaGetSymbolAddress((void**)&n2,  g_n2);
    cudaGetSymbolAddress((void**)&enc, g_enc);
    cudaGetSymbolAddress((void**)&kb,  g_k);
    cudaGetSymbolAddress((void**)&vb,  g_v);
    cudaGetSymbolAddress((void**)&q,   g_q);
    cudaGetSymbolAddress((void**)&oA,  g_oA);
    cudaGetSymbolAddress((void**)&m1,  g_m1);
    cudaGetSymbolAddress((void**)&m2,  g_m2);
    cudaGetSymbolAddress((void**)&w2bt, g_w2bt);
    cudaGetSymbolAddress((void**)&wh,  g_wh);
    cudaGetSymbolAddress((void**)&wl,  g_wl);

    cudaFuncSetAttribute(edge_pers, cudaFuncAttributeMaxDynamicSharedMemorySize, EDGE9_SMEM);
    cudaFuncSetAttribute(gemm_b3, cudaFuncAttributeMaxDynamicSharedMemorySize, B3_SMEM);
    cudaFuncSetAttribute(gemm_b3_qkv, cudaFuncAttributeMaxDynamicSharedMemorySize, B3_SMEM);

    const uint32_t *WI = wh + 0, *WJ = wh + 256 * 128, *GN1 = wh + 512 * 128,
                   *GN2 = wh + 768 * 128, *GO = wh + 1024 * 128,
                   *MQ0 = wh + 1280 * 128, *MQ1 = wh + 1536 * 128, *MQ2 = wh + 1792 * 128,
                   *MK0 = wh + 2048 * 128, *MK1 = wh + 2304 * 128, *MK2 = wh + 2560 * 128,
                   *MV0 = wh + 2816 * 128, *MV1 = wh + 3072 * 128, *MV2 = wh + 3328 * 128,
                   *MO0 = wh + 3584 * 128, *MO1 = wh + 3840 * 128, *MO2 = wh + 4096 * 128,
                   *FIN = wh + 4352 * 128;
    const ptrdiff_t LO = wl - wh;

    // 0. prep
    WPtrs wp;
    wp.p[0] = geW1; wp.p[1] = geW1 + 65536;
    wp.p[2] = gnW1; wp.p[3] = gnW2; wp.p[4] = goW;
    wp.p[5] = mWq; wp.p[6] = mWq + 65536; wp.p[7] = mWq + 131072;
    wp.p[8] = mWk; wp.p[9] = mWk + 65536; wp.p[10] = mWk + 131072;
    wp.p[11] = mWv; wp.p[12] = mWv + 65536; wp.p[13] = mWv + 131072;
    wp.p[14] = mWo; wp.p[15] = mWo + 65536; wp.p[16] = mWo + 131072;
    wp.p[17] = finW;
    prep_all<<<4992, 128>>>(wp, geW2, wh, wl, w2bt);

    // 1. h = x @ gin_W + gin_b   (K=48, fp32)
    gemm_kernel<<<dim3(8, 64), 256>>>(x, ginW, ginb, nullptr, h, 1024, 48, 256, 0);
    // 2+3. hi = h@Wi ; hj = h@Wj + geb1
    gemm_b3_qkv<<<dim3(8, 32), 256, B3_SMEM>>>(h, h, h, WI, WJ, WI, WI + LO, WJ + LO, WI + LO,
                                               nullptr, geb1, nullptr, hi, hj, hi,
                                               1024, 1024, 1024);
    // 4. fused edge MLP + adjacency contraction (persistent) -> agg
    edge_pers<<<148, 512, EDGE9_SMEM>>>(hi, hj, w2bt, geb2, adj, agg);
    // 5-7. node MLP + encoder
    gemm_b3<<<dim3(4, 32), 256, B3_SMEM>>>(agg, GN1, GN1 + LO, gnb1, nullptr, n1, 1024, 256, 1);
    gemm_b3<<<dim3(4, 32), 256, B3_SMEM>>>(n1,  GN2, GN2 + LO, gnb2, nullptr, n2, 1024, 256, 1);
    gemm_b3<<<dim3(4, 32), 256, B3_SMEM>>>(n2,  GO,  GO  + LO, gob,  nullptr, enc, 1024, 256, 0);

    // ---- MAB 0: q/k/v in ONE launch (q: A=S, M=16) ----
    gemm_b3_qkv<<<dim3(12, 32), 256, B3_SMEM>>>(enc, enc, S, MK0, MV0, MQ0,
                                                MK0 + LO, MV0 + LO, MQ0 + LO,
                                                mbk, mbv, mbq, kb, vb, q,
                                                1024, 1024, 16);
    attn_kernel<<<dim3(8, 4), 256>>>(q, 0, kb, vb, 256, oA);
    gemm_b3<<<dim3(4, 2), 256, B3_SMEM>>>(oA, MO0, MO0 + LO, mbo, oA, m1, 64, 256, 1);

    // ---- MAB 1 ----
    gemm_b3_qkv<<<dim3(12, 2), 256, B3_SMEM>>>(m1, m1, m1, MQ1, MK1, MV1,
                                               MQ1 + LO, MK1 + LO, MV1 + LO,
                                               mbq + 256, mbk + 256, mbv + 256, q, kb, vb,
                                               64, 64, 64);
    attn_kernel<<<dim3(8, 4), 256>>>(q, 16 * 256, kb, vb, 16, oA);
    gemm_b3<<<dim3(4, 2), 256, B3_SMEM>>>(oA, MO1, MO1 + LO, mbo + 256, oA, m2, 64, 256, 1);

    // ---- MAB 2 ----
    gemm_b3_qkv<<<dim3(12, 2), 256, B3_SMEM>>>(m2, m2, m2, MQ2, MK2, MV2,
                                               MQ2 + LO, MK2 + LO, MV2 + LO,
                                               mbq + 512, mbk + 512, mbv + 512, q, kb, vb,
                                               64, 64, 64);
    attn_kernel<<<dim3(8, 4), 256>>>(q, 16 * 256, kb, vb, 16, oA);
    gemm_b3<<<dim3(4, 2), 256, B3_SMEM>>>(oA, MO2, MO2 + LO, mbo + 512, oA, m1, 64, 256, 1);

    // ---- final ----
    gemm_b3<<<dim3(6, 2), 256, B3_SMEM>>>(m1, FIN, FIN + LO, finb, nullptr, out, 64, 384, 0);
}

// round 17
// speedup vs baseline: 1.0067x; 1.0067x over previous
#include <cuda_runtime.h>
#include <cuda_bf16.h>
#include <cstdint>
#include <math.h>
#include <stddef.h>

// ---------------- scratch (device globals; no allocations allowed) ----------
__device__ float g_h  [1024 * 256];
__device__ float g_hi [1024 * 256];
__device__ float g_hj [1024 * 256];
__device__ float g_agg[1024 * 256];
__device__ float g_n1 [1024 * 256];
__device__ float g_n2 [1024 * 256];
__device__ float g_enc[1024 * 256];
__device__ float g_k  [1024 * 256];
__device__ float g_v  [1024 * 256];
__device__ float g_q  [64 * 256];
__device__ float g_oA [64 * 256];
__device__ float g_m1 [64 * 256];
__device__ float g_m2 [64 * 256];
__device__ uint32_t g_w2bt[256 * 128];      // edge W2: [n][k/2] bf16x2
// split-bf16 chain weights: 18 matrices, [n][k/2] packed, hi + lo parts.
__device__ uint32_t g_wh[4736 * 128];
__device__ uint32_t g_wl[4736 * 128];

struct WPtrs { const float* p[18]; };

// ---------------- helpers ----------------------------------------------------
__device__ __forceinline__ uint32_t pack_bf16x2(float lo, float hi) {
    __nv_bfloat162 p = __floats2bfloat162_rn(lo, hi);
    return *(uint32_t*)&p;
}
__device__ __forceinline__ void mma_bf16(float* c, const uint32_t* a, const uint32_t* bf) {
    asm volatile(
        "mma.sync.aligned.m16n8k16.row.col.f32.bf16.bf16.f32 "
        "{%0,%1,%2,%3}, {%4,%5,%6,%7}, {%8,%9}, {%0,%1,%2,%3};"
        : "+f"(c[0]), "+f"(c[1]), "+f"(c[2]), "+f"(c[3])
        : "r"(a[0]), "r"(a[1]), "r"(a[2]), "r"(a[3]), "r"(bf[0]), "r"(bf[1]));
}
__device__ __forceinline__ void ldsm_x4(uint32_t* r, uint32_t saddr) {
    asm volatile("ldmatrix.sync.aligned.m8n8.x4.shared.b16 {%0,%1,%2,%3}, [%4];"
        : "=r"(r[0]), "=r"(r[1]), "=r"(r[2]), "=r"(r[3]) : "r"(saddr));
}
__device__ __forceinline__ void split_bf16(float x, __nv_bfloat16& h, __nv_bfloat16& l) {
    h = __float2bfloat16(x);
    l = __float2bfloat16(x - __bfloat162float(h));
}

// ---------------- prep: chain weights (split-bf16) + edge W2, one launch ----
__global__ void prep_all(WPtrs wp, const float* __restrict__ W2,
                         uint32_t* __restrict__ wh, uint32_t* __restrict__ wl,
                         uint32_t* __restrict__ w2bt) {
    const int c = threadIdx.x;
    if (blockIdx.x >= 4736) {
        int n = blockIdx.x - 4736;
        w2bt[n * 128 + c] = pack_bf16x2(W2[(2 * c) * 256 + n], W2[(2 * c + 1) * 256 + n]);
        return;
    }
    const int row = blockIdx.x;
    const int m = row < 4352 ? (row >> 8) : 17;
    const int n = row - (m < 17 ? (m << 8) : 4352);
    const int N = (m == 17) ? 384 : 256;
    const float* W = wp.p[m];
    float w0 = W[(size_t)(2 * c) * N + n];
    float w1 = W[(size_t)(2 * c + 1) * N + n];
    __nv_bfloat16 h0, l0, h1, l1;
    split_bf16(w0, h0, l0);
    split_bf16(w1, h1, l1);
    wh[(size_t)row * 128 + c] = pack_bf16x2(__bfloat162float(h0), __bfloat162float(h1));
    wl[(size_t)row * 128 + c] = pack_bf16x2(__bfloat162float(l0), __bfloat162float(l1));
}

// ---------------- split-bf16 tensor GEMM core (32m x 64n, 256 thr) -----------
static constexpr int B3P = 132;
static constexpr int B3_AH = 0;
static constexpr int B3_AL = 32 * B3P;
static constexpr int B3_WH = 2 * 32 * B3P;
static constexpr int B3_WL = B3_WH + 64 * B3P;
static constexpr int B3_U32 = B3_WL + 64 * B3P;
static constexpr int B3_SMEM = B3_U32 * 4;          // 101376 B (2 CTAs/SM)

__device__ __forceinline__ void b3_core(
    const float* __restrict__ A, const uint32_t* __restrict__ wh,
    const uint32_t* __restrict__ wl, const float* __restrict__ bias,
    const float* __restrict__ res, float* __restrict__ Cg,
    int M, int N, int act, int rowB, int colB, uint32_t* sm)
{
    const int tid = threadIdx.x, lane = tid & 31, w = tid >> 5;
    const int g = lane >> 2, tg = lane & 3;
    const int wm = w & 1, wn = w >> 1;

    // ---- two-phase fills: batch ALL global loads first (force MLP) ----
    const int arow = tid >> 3, af4 = tid & 7;
    float4 avs[8];
    {
        const int gr = rowB + arow;
        const float* Ar = A + (size_t)gr * 256;
        #pragma unroll
        for (int p = 0; p < 8; ++p) {
            const int col = p * 8 + af4;
            avs[p] = (gr < M) ? *(const float4*)(Ar + col * 4)
                              : make_float4(0.f, 0.f, 0.f, 0.f);
        }
    }
    uint4 vhs[8], vls[8];
    {
        #pragma unroll
        for (int p = 0; p < 8; ++p) {
            const int idx = p * 256 + tid;
            const int n = idx >> 5, c4 = idx & 31;
            vhs[p] = *(const uint4*)(wh + (size_t)(colB + n) * 128 + c4 * 4);
            vls[p] = *(const uint4*)(wl + (size_t)(colB + n) * 128 + c4 * 4);
        }
    }
    // phase 2: convert + store
    #pragma unroll
    for (int p = 0; p < 8; ++p) {
        const int col = p * 8 + af4;
        __nv_bfloat16 h0,l0,h1,l1,h2,l2,h3,l3;
        split_bf16(avs[p].x, h0, l0); split_bf16(avs[p].y, h1, l1);
        split_bf16(avs[p].z, h2, l2); split_bf16(avs[p].w, h3, l3);
        uint2 oh, ol;
        oh.x = pack_bf16x2(__bfloat162float(h0), __bfloat162float(h1));
        oh.y = pack_bf16x2(__bfloat162float(h2), __bfloat162float(h3));
        ol.x = pack_bf16x2(__bfloat162float(l0), __bfloat162float(l1));
        ol.y = pack_bf16x2(__bfloat162float(l2), __bfloat162float(l3));
        *(uint2*)(sm + B3_AH + arow * B3P + col * 2) = oh;
        *(uint2*)(sm + B3_AL + arow * B3P + col * 2) = ol;
    }
    #pragma unroll
    for (int p = 0; p < 8; ++p) {
        const int idx = p * 256 + tid;
        const int n = idx >> 5, c4 = idx & 31;
        *(uint4*)(sm + B3_WH + n * B3P + c4 * 4) = vhs[p];
        *(uint4*)(sm + B3_WL + n * B3P + c4 * 4) = vls[p];
    }
    __syncthreads();

    const uint32_t smemS = (uint32_t)__cvta_generic_to_shared(sm);
    const uint32_t aTh = (uint32_t)((lane & 15) * (B3P * 4) + (lane >> 4) * 16);
    const uint32_t wTh = (uint32_t)((((lane >> 4) & 1) * 8 + (lane & 7)) * (B3P * 4)
                                    + ((lane >> 3) & 1) * 16);
    const uint32_t Ah = smemS + B3_AH * 4 + wm * 16 * (B3P * 4) + aTh;
    const uint32_t Al = smemS + B3_AL * 4 + wm * 16 * (B3P * 4) + aTh;
    const uint32_t Wh = smemS + B3_WH * 4 + wn * 16 * (B3P * 4) + wTh;
    const uint32_t Wl = smemS + B3_WL * 4 + wn * 16 * (B3P * 4) + wTh;

    float C[2][4] = {{0.f,0.f,0.f,0.f},{0.f,0.f,0.f,0.f}};
    #pragma unroll
    for (int ks = 0; ks < 16; ++ks) {
        uint32_t ahi[4], alo[4], th[4], tl[4];
        ldsm_x4(ahi, Ah + ks * 32);
        ldsm_x4(alo, Al + ks * 32);
        ldsm_x4(th, Wh + ks * 32);
        ldsm_x4(tl, Wl + ks * 32);
        uint32_t whi[2][2] = {{th[0], th[1]}, {th[2], th[3]}};
        uint32_t wlo[2][2] = {{tl[0], tl[1]}, {tl[2], tl[3]}};
        #pragma unroll
        for (int nt = 0; nt < 2; ++nt) {
            mma_bf16(C[nt], ahi, whi[nt]);
            mma_bf16(C[nt], ahi, wlo[nt]);
            mma_bf16(C[nt], alo, whi[nt]);
        }
    }

    #pragma unroll
    for (int nt = 0; nt < 2; ++nt) {
        #pragma unroll
        for (int rr = 0; rr < 2; ++rr) {
            const int m = rowB + wm * 16 + g + rr * 8;
            if (m < M) {
                #pragma unroll
                for (int cc = 0; cc < 2; ++cc) {
                    const int col = colB + wn * 16 + nt * 8 + 2 * tg + cc;
                    float v = C[nt][rr * 2 + cc] + (bias ? bias[col] : 0.f);
                    if (act) v = fmaxf(v, 0.f);
                    if (res) v += res[(size_t)m * N + col];
                    Cg[(size_t)m * N + col] = v;
                }
            }
        }
    }
}

__global__ void __launch_bounds__(256)
gemm_b3(const float* A, const uint32_t* wh, const uint32_t* wl,
        const float* bias, const float* res, float* Cg, int M, int N, int act)
{
    extern __shared__ uint32_t sm[];
    b3_core(A, wh, wl, bias, res, Cg, M, N, act,
            blockIdx.y * 32, blockIdx.x * 64, sm);
}

// fused multi-matrix (N=256): per-sel A/M; early-exit rows beyond M(sel).
__global__ void __launch_bounds__(256)
gemm_b3_qkv(const float* A0, const float* A1, const float* A2,
            const uint32_t* wh0, const uint32_t* wh1, const uint32_t* wh2,
            const uint32_t* wl0, const uint32_t* wl1, const uint32_t* wl2,
            const float* b0, const float* b1, const float* b2,
            float* C0, float* C1, float* C2, int M0, int M1, int M2)
{
    extern __shared__ uint32_t sm[];
    const int sel = blockIdx.x >> 2;
    const float* A     = sel == 0 ? A0 : (sel == 1 ? A1 : A2);
    const int M        = sel == 0 ? M0 : (sel == 1 ? M1 : M2);
    if ((int)blockIdx.y * 32 >= M) return;
    const uint32_t* wh = sel == 0 ? wh0 : (sel == 1 ? wh1 : wh2);
    const uint32_t* wl = sel == 0 ? wl0 : (sel == 1 ? wl1 : wl2);
    const float* bias  = sel == 0 ? b0 : (sel == 1 ? b1 : b2);
    float* Cg          = sel == 0 ? C0 : (sel == 1 ? C1 : C2);
    b3_core(A, wh, wl, bias, nullptr, Cg, M, 256, 0,
            blockIdx.y * 32, (blockIdx.x & 3) * 64, sm);
}

// ---------------- edge v9: persistent CTAs (best known: ~105-106 us) --------
static constexpr int APW = 68;
static constexpr int WPW = 132;
static constexpr int EV_A  = 128 * APW;
static constexpr int EV_W  = 256 * WPW;
static constexpr int EV_U32 = 2 * EV_A + EV_W;            // 51200
static constexpr int EDGE9_SMEM = (EV_U32 + 1540) * 4;    // 210960 B

__global__ void __launch_bounds__(512, 1)
edge_pers(const float* __restrict__ hi, const float* __restrict__ hjp,
          const uint32_t* __restrict__ w2bt, const float* __restrict__ b2,
          const float* __restrict__ adj, float* __restrict__ agg)
{
    extern __shared__ uint32_t smu[];
    uint32_t* Abufs = smu;
    uint32_t* Wbuf  = smu + 2 * EV_A;
    float* ci    = (float*)(smu + EV_U32);
    float* b2s   = ci + 256;
    float* wlist = b2s + 256;
    float* part  = wlist + 256;                 // 512
    int*   idxs  = (int*)(part + 512);          // 256
    int*   cntp  = idxs + 256;

    const int tid = threadIdx.x, lane = tid & 31, w = tid >> 5;

    const int g  = lane >> 2;
    const int tg = lane & 3;
    const int jm = w & 1;
    const int hn = w >> 1;
    const int kq = lane;
    const int jr = w;

    const uint32_t smemS = (uint32_t)__cvta_generic_to_shared(smu);
    const uint32_t aTh = (uint32_t)((lane & 15) * (APW * 4) + (lane >> 4) * 16);
    const uint32_t wTh = (uint32_t)((((lane >> 4) & 1) * 8 + (lane & 7)) * (WPW * 4)
                                    + ((lane >> 3) & 1) * 16);
    const uint32_t Wbase = smemS + 2 * EV_A * 4 + hn * 32 * (WPW * 4) + wTh;

    #pragma unroll
    for (int p = 0; p < 16; ++p) {
        const int r = p * 16 + jr;
        uint4 wv = *(const uint4*)(w2bt + (size_t)r * 128 + kq * 4);
        *(uint4*)(Wbuf + r * WPW + kq * 4) = wv;
    }
    if (tid < 256) b2s[tid] = b2[tid];

    float C[4][4][4];
    #pragma unroll
    for (int mt = 0; mt < 4; ++mt)
        #pragma unroll
        for (int nt = 0; nt < 4; ++nt)
            #pragma unroll
            for (int r = 0; r < 4; ++r) C[mt][nt][r] = 0.f;

    for (int tile = blockIdx.x; tile < 1024; tile += gridDim.x) {
        const int i = tile & 255, b = tile >> 8;
        const size_t row = (size_t)(b * 256 + i) * 256;
        const float* hjb = hjp + (size_t)b * 65536;

        __syncthreads();
        if (tid == 0) *cntp = 0;
        __syncthreads();
        if (tid < 256) {
            ci[tid] = hi[row + tid];
            float a = adj[row + tid];
            if (a != 0.f) {
                int p = atomicAdd(cntp, 1);
                idxs[p]  = tid;
                wlist[p] = a;
            }
        }
        __syncthreads();
        const int nj = *cntp;
        const int npass = (nj + 127) >> 7;
        for (int r = nj + tid; r < npass * 128; r += 512) { wlist[r] = 0.f; idxs[r] = 0; }

        const float4 cv0 = *(const float4*)(ci + kq * 4);
        const float4 cv1 = *(const float4*)(ci + 128 + kq * 4);

        auto fillA_pass = [&](int s, int p) {
            const int jt = s >> 1, kc = s & 1;
            const int r = p * 16 + jr;
            const int slot = jt * 128 + r;
            uint2 o = {0u, 0u};
            if (slot < nj) {
                const int j = idxs[slot];
                const float4 cv = kc ? cv1 : cv0;
                float4 hv = *(const float4*)(hjb + (size_t)j * 256 + kc * 128 + kq * 4);
                o.x = pack_bf16x2(fmaxf(cv.x + hv.x, 0.f), fmaxf(cv.y + hv.y, 0.f));
                o.y = pack_bf16x2(fmaxf(cv.z + hv.z, 0.f), fmaxf(cv.w + hv.w, 0.f));
            }
            *(uint2*)(Abufs + (s & 1) * EV_A + r * APW + kq * 2) = o;
        };

        float ps[4][2];
        #pragma unroll
        for (int nt = 0; nt < 4; ++nt) { ps[nt][0] = 0.f; ps[nt][1] = 0.f; }

        const int tsteps = 2 * npass;
        if (npass > 0) {
            #pragma unroll
            for (int p = 0; p < 8; ++p) fillA_pass(0, p);
        }
        __syncthreads();

        for (int s = 0; s < tsteps; ++s) {
            const int kc = s & 1, jt = s >> 1;
            const uint32_t Abase = smemS + (uint32_t)((s & 1) * EV_A * 4)
                                 + jm * 64 * (APW * 4) + aTh;
            const uint32_t Wk = Wbase + (uint32_t)(kc * 256);
            #pragma unroll
            for (int ks = 0; ks < 8; ++ks) {
                uint32_t afr[4][4], bfr[4][2];
                #pragma unroll
                for (int mt = 0; mt < 4; ++mt)
                    ldsm_x4(afr[mt], Abase + mt * 16 * (APW * 4) + ks * 32);
                #pragma unroll
                for (int p = 0; p < 2; ++p) {
                    uint32_t tmp[4];
                    ldsm_x4(tmp, Wk + p * 16 * (WPW * 4) + ks * 32);
                    bfr[2 * p][0] = tmp[0]; bfr[2 * p][1] = tmp[1];
                    bfr[2 * p + 1][0] = tmp[2]; bfr[2 * p + 1][1] = tmp[3];
                }
                #pragma unroll
                for (int mt = 0; mt < 4; ++mt)
                    #pragma unroll
                    for (int nt = 0; nt < 4; ++nt)
                        mma_bf16(C[mt][nt], afr[mt], bfr[nt]);
                if (s + 1 < tsteps) fillA_pass(s + 1, ks);
            }
            if (kc == 1) {
                #pragma unroll
                for (int mt = 0; mt < 4; ++mt) {
                    const float aj0 = wlist[jt * 128 + jm * 64 + mt * 16 + g];
                    const float aj8 = wlist[jt * 128 + jm * 64 + mt * 16 + g + 8];
                    #pragma unroll
                    for (int nt = 0; nt < 4; ++nt) {
                        #pragma unroll
                        for (int c = 0; c < 2; ++c) {
                            const float bv = b2s[hn * 32 + nt * 8 + 2 * tg + c];
                            ps[nt][c] += aj0 * fmaxf(C[mt][nt][c]     + bv, 0.f)
                                       + aj8 * fmaxf(C[mt][nt][2 + c] + bv, 0.f);
                            C[mt][nt][c] = 0.f;
                            C[mt][nt][2 + c] = 0.f;
                        }
                    }
                }
            }
            __syncthreads();
        }

        #pragma unroll
        for (int off = 16; off >= 4; off >>= 1)
            #pragma unroll
            for (int nt = 0; nt < 4; ++nt)
                #pragma unroll
                for (int c = 0; c < 2; ++c)
                    ps[nt][c] += __shfl_down_sync(0xffffffffu, ps[nt][c], off);
        if (lane < 4) {
            #pragma unroll
            for (int nt = 0; nt < 4; ++nt)
                #pragma unroll
                for (int c = 0; c < 2; ++c)
                    part[w * 32 + nt * 8 + 2 * lane + c] = ps[nt][c];
        }
        __syncthreads();
        if (tid < 256) {
            const int hq = tid >> 5, hl = tid & 31;
            agg[row + tid] = part[(2 * hq) * 32 + hl] + part[(2 * hq + 1) * 32 + hl];
        }
    }
}

// ---------------- fp32 GEMM (used only for h: K=48) -------------------------
__global__ void gemm_kernel(const float* __restrict__ A, const float* __restrict__ W,
                            const float* __restrict__ bias, const float* __restrict__ res,
                            float* __restrict__ C, int M, int K, int N, int act)
{
    __shared__ float As[32 * 18];
    __shared__ float Ws[32 * 33];
    const int tid  = threadIdx.x;
    const int lane = tid & 31;
    const int ty   = tid >> 5;
    const int colB = blockIdx.x * 32;
    const int rowB = blockIdx.y * 16;

    float acc[2] = {0.f, 0.f};
    for (int k0 = 0; k0 < K; k0 += 32) {
        #pragma unroll
        for (int u = 0; u < 2; ++u) {
            int idx = tid + u * 256, r = idx >> 5, c = idx & 31;
            int gr = rowB + r, gk = k0 + c;
            As[c * 18 + r] = (gr < M && gk < K) ? A[(size_t)gr * K + gk] : 0.f;
        }
        #pragma unroll
        for (int u = 0; u < 4; ++u) {
            int idx = tid + u * 256, r = idx >> 5, c = idx & 31;
            int gk = k0 + r, gn = colB + c;
            Ws[r * 33 + c] = (gk < K && gn < N) ? W[(size_t)gk * N + gn] : 0.f;
        }
        __syncthreads();
        #pragma unroll
        for (int kk = 0; kk < 32; ++kk) {
            float2 av = *(const float2*)(As + kk * 18 + ty * 2);
            float wv = Ws[kk * 33 + lane];
            acc[0] = fmaf(av.x, wv, acc[0]);
            acc[1] = fmaf(av.y, wv, acc[1]);
        }
        __syncthreads();
    }
    int col = colB + lane;
    if (col < N) {
        float bv = bias ? bias[col] : 0.f;
        #pragma unroll
        for (int r = 0; r < 2; ++r) {
            int rowi = rowB + ty * 2 + r;
            if (rowi < M) {
                float v = acc[r] + bv;
                if (act) v = fmaxf(v, 0.f);
                if (res) v += res[(size_t)rowi * N + col];
                C[(size_t)rowi * N + col] = v;
            }
        }
    }
}

// ---------------- multi-head attention core ---------------------------------
__global__ void attn_kernel(const float* __restrict__ q, int q_bs,
                            const float* __restrict__ k, const float* __restrict__ v,
                            int Lk, float* __restrict__ o)
{
    __shared__ float qs[16 * 32];
    __shared__ float sc[16 * 256];
    const int tid  = threadIdx.x;
    const int head = blockIdx.x;
    const int b    = blockIdx.y;

    const float* qb = q + (size_t)b * q_bs;
    for (int u = tid; u < 512; u += 256) {
        int l = u >> 5, d = u & 31;
        qs[u] = qb[(size_t)l * 256 + head * 32 + d];
    }
    __syncthreads();

    {
        int l = tid & 15, jg = tid >> 4;
        const float* kb = k + ((size_t)b * Lk) * 256 + head * 32;
        for (int j = jg; j < Lk; j += 16) {
            const float* kr = kb + (size_t)j * 256;
            float s = 0.f;
            #pragma unroll
            for (int d = 0; d < 32; ++d) s = fmaf(qs[l * 32 + d], kr[d], s);
            sc[l * 256 + j] = s * 0.0625f;
        }
    }
    __syncthreads();

    if (tid < 16) {
        float m = -1e30f;
        for (int j = 0; j < Lk; ++j) m = fmaxf(m, sc[tid * 256 + j]);
        float sum = 0.f;
        for (int j = 0; j < Lk; ++j) {
            float e = __expf(sc[tid * 256 + j] - m);
            sc[tid * 256 + j] = e;
            sum += e;
        }
        float inv = 1.f / sum;
        for (int j = 0; j < Lk; ++j) sc[tid * 256 + j] *= inv;
    }
    __syncthreads();

    {
        const float* vb = v + ((size_t)b * Lk) * 256 + head * 32;
        for (int u = tid; u < 512; u += 256) {
            int l = u >> 5, d = u & 31;
            float accv = qs[l * 32 + d];
            for (int j = 0; j < Lk; ++j)
                accv = fmaf(sc[l * 256 + j], vb[(size_t)j * 256 + d], accv);
            o[((size_t)(b * 16 + l)) * 256 + head * 32 + d] = accv;
        }
    }
}

// ---------------- host orchestration ---------------------------------------
extern "C" void kernel_launch(void* const* d_in, const int* in_sizes, int n_in,
                              void* d_out, int out_size)
{
    (void)in_sizes; (void)n_in; (void)out_size;
    const float* x    = (const float*)d_in[0];
    const float* adj  = (const float*)d_in[1];
    const float* ginW = (const float*)d_in[2];
    const float* ginb = (const float*)d_in[3];
    const float* geW1 = (const float*)d_in[4];
    const float* geb1 = (const float*)d_in[5];
    const float* geW2 = (const float*)d_in[6];
    const float* geb2 = (const float*)d_in[7];
    const float* gnW1 = (const float*)d_in[8];
    const float* gnb1 = (const float*)d_in[9];
    const float* gnW2 = (const float*)d_in[10];
    const float* gnb2 = (const float*)d_in[11];
    const float* goW  = (const float*)d_in[12];
    const float* gob  = (const float*)d_in[13];
    const float* S    = (const float*)d_in[14];
    const float* mWq  = (const float*)d_in[15];
    const float* mbq  = (const float*)d_in[16];
    const float* mWk  = (const float*)d_in[17];
    const float* mbk  = (const float*)d_in[18];
    const float* mWv  = (const float*)d_in[19];
    const float* mbv  = (const float*)d_in[20];
    const float* mWo  = (const float*)d_in[21];
    const float* mbo  = (const float*)d_in[22];
    const float* finW = (const float*)d_in[23];
    const float* finb = (const float*)d_in[24];
    float* out = (float*)d_out;

    float *h, *hi, *hj, *agg, *n1, *n2, *enc, *kb, *vb, *q, *oA, *m1, *m2;
    uint32_t *w2bt, *wh, *wl;
    cudaGetSymbolAddress((void**)&h,   g_h);
    cudaGetSymbolAddress((void**)&hi,  g_hi);
    cudaGetSymbolAddress((void**)&hj,  g_hj);
    cudaGetSymbolAddress((void**)&agg, g_agg);
    cudaGetSymbolAddress((void**)&n1,  g_n1);
    cudaGetSymbolAddress((void**)&n2,  g_n2);
    cudaGetSymbolAddress((void**)&enc, g_enc);
    cudaGetSymbolAddress((void**)&kb,  g_k);
    cudaGetSymbolAddress((void**)&vb,  g_v);
    cudaGetSymbolAddress((void**)&q,   g_q);
    cudaGetSymbolAddress((void**)&oA,  g_oA);
    cudaGetSymbolAddress((void**)&m1,  g_m1);
    cudaGetSymbolAddress((void**)&m2,  g_m2);
    cudaGetSymbolAddress((void**)&w2bt, g_w2bt);
    cudaGetSymbolAddress((void**)&wh,  g_wh);
    cudaGetSymbolAddress((void**)&wl,  g_wl);

    cudaFuncSetAttribute(edge_pers, cudaFuncAttributeMaxDynamicSharedMemorySize, EDGE9_SMEM);
    cudaFuncSetAttribute(gemm_b3, cudaFuncAttributeMaxDynamicSharedMemorySize, B3_SMEM);
    cudaFuncSetAttribute(gemm_b3_qkv, cudaFuncAttributeMaxDynamicSharedMemorySize, B3_SMEM);

    const uint32_t *WI = wh + 0, *WJ = wh + 256 * 128, *GN1 = wh + 512 * 128,
                   *GN2 = wh + 768 * 128, *GO = wh + 1024 * 128,
                   *MQ0 = wh + 1280 * 128, *MQ1 = wh + 1536 * 128, *MQ2 = wh + 1792 * 128,
                   *MK0 = wh + 2048 * 128, *MK1 = wh + 2304 * 128, *MK2 = wh + 2560 * 128,
                   *MV0 = wh + 2816 * 128, *MV1 = wh + 3072 * 128, *MV2 = wh + 3328 * 128,
                   *MO0 = wh + 3584 * 128, *MO1 = wh + 3840 * 128, *MO2 = wh + 4096 * 128,
                   *FIN = wh + 4352 * 128;
    const ptrdiff_t LO = wl - wh;

    // 0. prep
    WPtrs wp;
    wp.p[0] = geW1; wp.p[1] = geW1 + 65536;
    wp.p[2] = gnW1; wp.p[3] = gnW2; wp.p[4] = goW;
    wp.p[5] = mWq; wp.p[6] = mWq + 65536; wp.p[7] = mWq + 131072;
    wp.p[8] = mWk; wp.p[9] = mWk + 65536; wp.p[10] = mWk + 131072;
    wp.p[11] = mWv; wp.p[12] = mWv + 65536; wp.p[13] = mWv + 131072;
    wp.p[14] = mWo; wp.p[15] = mWo + 65536; wp.p[16] = mWo + 131072;
    wp.p[17] = finW;
    prep_all<<<4992, 128>>>(wp, geW2, wh, wl, w2bt);

    // 1. h = x @ gin_W + gin_b   (K=48, fp32)
    gemm_kernel<<<dim3(8, 64), 256>>>(x, ginW, ginb, nullptr, h, 1024, 48, 256, 0);
    // 2+3. hi = h@Wi ; hj = h@Wj + geb1
    gemm_b3_qkv<<<dim3(8, 32), 256, B3_SMEM>>>(h, h, h, WI, WJ, WI, WI + LO, WJ + LO, WI + LO,
                                               nullptr, geb1, nullptr, hi, hj, hi,
                                               1024, 1024, 1024);
    // 4. fused edge MLP + adjacency contraction (persistent) -> agg
    edge_pers<<<148, 512, EDGE9_SMEM>>>(hi, hj, w2bt, geb2, adj, agg);
    // 5-7. node MLP + encoder
    gemm_b3<<<dim3(4, 32), 256, B3_SMEM>>>(agg, GN1, GN1 + LO, gnb1, nullptr, n1, 1024, 256, 1);
    gemm_b3<<<dim3(4, 32), 256, B3_SMEM>>>(n1,  GN2, GN2 + LO, gnb2, nullptr, n2, 1024, 256, 1);
    gemm_b3<<<dim3(4, 32), 256, B3_SMEM>>>(n2,  GO,  GO  + LO, gob,  nullptr, enc, 1024, 256, 0);

    // ---- MAB 0: q/k/v in ONE launch (q: A=S, M=16) ----
    gemm_b3_qkv<<<dim3(12, 32), 256, B3_SMEM>>>(enc, enc, S, MK0, MV0, MQ0,
                                                MK0 + LO, MV0 + LO, MQ0 + LO,
                                                mbk, mbv, mbq, kb, vb, q,
                                                1024, 1024, 16);
    attn_kernel<<<dim3(8, 4), 256>>>(q, 0, kb, vb, 256, oA);
    gemm_b3<<<dim3(4, 2), 256, B3_SMEM>>>(oA, MO0, MO0 + LO, mbo, oA, m1, 64, 256, 1);

    // ---- MAB 1 ----
    gemm_b3_qkv<<<dim3(12, 2), 256, B3_SMEM>>>(m1, m1, m1, MQ1, MK1, MV1,
                                               MQ1 + LO, MK1 + LO, MV1 + LO,
                                               mbq + 256, mbk + 256, mbv + 256, q, kb, vb,
                                               64, 64, 64);
    attn_kernel<<<dim3(8, 4), 256>>>(q, 16 * 256, kb, vb, 16, oA);
    gemm_b3<<<dim3(4, 2), 256, B3_SMEM>>>(oA, MO1, MO1 + LO, mbo + 256, oA, m2, 64, 256, 1);

    // ---- MAB 2 ----
    gemm_b3_qkv<<<dim3(12, 2), 256, B3_SMEM>>>(m2, m2, m2, MQ2, MK2, MV2,
                                               MQ2 + LO, MK2 + LO, MV2 + LO,
                                               mbq + 512, mbk + 512, mbv + 512, q, kb, vb,
                                               64, 64, 64);
    attn_kernel<<<dim3(8, 4), 256>>>(q, 16 * 256, kb, vb, 16, oA);
    gemm_b3<<<dim3(4, 2), 256, B3_SMEM>>>(oA, MO2, MO2 + LO, mbo + 512, oA, m1, 64, 256, 1);

    // ---- final ----
    gemm_b3<<<dim3(6, 2), 256, B3_SMEM>>>(m1, FIN, FIN + LO, finb, nullptr, out, 64, 384, 0);
}